// round 5
// baseline (speedup 1.0000x reference)
#include <cuda_runtime.h>

#define B_TOT   4096
#define T_STEPS 512
#define IN_W    4
#define H_DIM   64
#define G_DIM   256
#define TB      32
#define NTH     256
#define HS      34   // padded batch-row stride (floats) -> 2-way max STS conflict

typedef unsigned long long ull;

// ---- sm_103a packed f32x2 helpers ----
__device__ __forceinline__ ull splat2(float x) {
    ull r; asm("mov.b64 %0, {%1, %1};" : "=l"(r) : "f"(x)); return r;
}
__device__ __forceinline__ ull pack2(float lo, float hi) {
    ull r; asm("mov.b64 %0, {%1, %2};" : "=l"(r) : "f"(lo), "f"(hi)); return r;
}
__device__ __forceinline__ ull fma2(ull a, ull b, ull c) {
    ull d; asm("fma.rn.f32x2 %0, %1, %2, %3;" : "=l"(d) : "l"(a), "l"(b), "l"(c)); return d;
}
__device__ __forceinline__ float2 unpack2(ull v) {
    float2 f; asm("mov.b64 {%0, %1}, %2;" : "=f"(f.x), "=f"(f.y) : "l"(v)); return f;
}

__device__ __forceinline__ float sigf(float x) {
    // x -> -inf: expf(+big)->inf, 1/inf -> 0 : safe
    return __fdividef(1.f, 1.f + __expf(-x));
}
__device__ __forceinline__ float tanh_fast(float x) {
    // overflow-safe: exp argument always <= 0
    float ax = fabsf(x);
    float e  = __expf(-2.f * ax);
    float r  = __fdividef(1.f - e, 1.f + e);
    return copysignf(r, x);
}

// SMEM layout (floats):
//  W1   [64][256]  @ 0       (Whh0, transposed, gate-interleaved [k][j][g])
//  W2   [128][256] @ 16384   (rows 0..63: Wih1, rows 64..127: Whh1)
//  h1b  [64][HS]   @ 49152   (h1 state, [unit][batch])
//  h2b  [128][HS]  @ 51328   (rows 0..63: h1_t, rows 64..127: h2 state)
//  xb   [4][HS]    @ 55680   (x_t, [in_feature][batch])
#define SM_W2   16384
#define SM_H1B  49152
#define SM_H2B  51328
#define SM_XB   55680
#define SM_TOT  55816   // floats = 223264 bytes

__global__ void __launch_bounds__(NTH, 1) lstm2_fused_kernel(
    const float* __restrict__ x,
    const float* __restrict__ Wih0, const float* __restrict__ Whh0,
    const float* __restrict__ bih0, const float* __restrict__ bhh0,
    const float* __restrict__ Wih1, const float* __restrict__ Whh1,
    const float* __restrict__ bih1, const float* __restrict__ bhh1,
    const float* __restrict__ Wfc,  const float* __restrict__ bfc,
    float* __restrict__ out)
{
    extern __shared__ float sm[];
    float* W1  = sm;
    float* W2  = sm + SM_W2;
    float* h1b = sm + SM_H1B;
    float* h2b = sm + SM_H2B;
    float* xb  = sm + SM_XB;

    const int tid = threadIdx.x;
    const int j   = tid & 63;   // gate unit
    const int q   = tid >> 6;   // batch quarter (8 batches each)
    const int b0  = blockIdx.x * TB;

    // ---- prologue: stage weights into SMEM, transposed + gate-interleaved ----
    for (int idx = tid; idx < 64 * 256; idx += NTH) {
        int k = idx >> 8, col = idx & 255;
        int r = ((col & 3) << 6) | (col >> 2);   // original gate row
        W1[idx] = Whh0[r * 64 + k];
    }
    for (int idx = tid; idx < 128 * 256; idx += NTH) {
        int k = idx >> 8, col = idx & 255;
        int r = ((col & 3) << 6) | (col >> 2);
        W2[idx] = (k < 64) ? Wih1[r * 64 + k] : Whh1[r * 64 + (k - 64)];
    }
    for (int idx = tid; idx < 64 * HS;  idx += NTH) h1b[idx] = 0.f;
    for (int idx = tid; idx < 128 * HS; idx += NTH) h2b[idx] = 0.f;
    if (tid < TB) {
        const float4 x4 = *(const float4*)(x + ((size_t)(b0 + tid) * T_STEPS) * IN_W);
        xb[0 * HS + tid] = x4.x; xb[1 * HS + tid] = x4.y;
        xb[2 * HS + tid] = x4.z; xb[3 * HS + tid] = x4.w;
    }

    // per-thread constants: input weights (layer1) + fused biases (pre-splatted)
    float wx[4][4];
    ull bs1[4], bs2[4];
    #pragma unroll
    for (int gg = 0; gg < 4; gg++) {
        int r = gg * 64 + j;
        #pragma unroll
        for (int ii = 0; ii < IN_W; ii++) wx[gg][ii] = Wih0[r * IN_W + ii];
        bs1[gg] = splat2(bih0[r] + bhh0[r]);
        bs2[gg] = splat2(bih1[r] + bhh1[r]);
    }

    float c1[8], c2[8];
    #pragma unroll
    for (int i = 0; i < 8; i++) { c1[i] = 0.f; c2[i] = 0.f; }

    __syncthreads();

    const float4* W1v = (const float4*)W1;
    const float4* W2v = (const float4*)W2;
    const int q8 = q * 8;

    for (int t = 0; t < T_STEPS; t++) {
        // ================= Phase A: layer-1 gates =================
        ull acc[4][4];
        #pragma unroll
        for (int gg = 0; gg < 4; gg++)
            #pragma unroll
            for (int p = 0; p < 4; p++)
                acc[gg][p] = bs1[gg];

        // x_t contribution (K=4, weights in registers)
        #pragma unroll
        for (int ii = 0; ii < IN_W; ii++) {
            ull xw0 = splat2(wx[0][ii]), xw1 = splat2(wx[1][ii]);
            ull xw2 = splat2(wx[2][ii]), xw3 = splat2(wx[3][ii]);
            const ull* xp = (const ull*)(xb + ii * HS + q8);
            #pragma unroll
            for (int p = 0; p < 4; p++) {
                ull xv = xp[p];
                acc[0][p] = fma2(xv, xw0, acc[0][p]);
                acc[1][p] = fma2(xv, xw1, acc[1][p]);
                acc[2][p] = fma2(xv, xw2, acc[2][p]);
                acc[3][p] = fma2(xv, xw3, acc[3][p]);
            }
        }
        // h1_{t-1} @ Whh0^T  (K=64)
        #pragma unroll 4
        for (int k = 0; k < 64; k++) {
            float4 w4 = W1v[(k << 6) | j];
            ull w0 = splat2(w4.x), w1 = splat2(w4.y);
            ull w2 = splat2(w4.z), w3 = splat2(w4.w);
            const ull* hp = (const ull*)(h1b + k * HS + q8);
            #pragma unroll
            for (int p = 0; p < 4; p++) {
                ull hv = hp[p];
                acc[0][p] = fma2(hv, w0, acc[0][p]);
                acc[1][p] = fma2(hv, w1, acc[1][p]);
                acc[2][p] = fma2(hv, w2, acc[2][p]);
                acc[3][p] = fma2(hv, w3, acc[3][p]);
            }
        }
        __syncthreads();   // sync1: all gates read h1b/xb before overwrite

        // ================= Phase B: layer-1 elementwise =================
        float4 xnext;
        const bool ldx = (tid < TB) && (t + 1 < T_STEPS);
        if (ldx)
            xnext = *(const float4*)(x + ((size_t)(b0 + tid) * T_STEPS + (t + 1)) * IN_W);

        #pragma unroll
        for (int p = 0; p < 4; p++) {
            float2 gi = unpack2(acc[0][p]);
            float2 gf = unpack2(acc[1][p]);
            float2 gc = unpack2(acc[2][p]);
            float2 go = unpack2(acc[3][p]);
            float i0 = sigf(gi.x),      i1 = sigf(gi.y);
            float f0 = sigf(gf.x),      f1 = sigf(gf.y);
            float g0 = tanh_fast(gc.x), g1 = tanh_fast(gc.y);
            float o0 = sigf(go.x),      o1 = sigf(go.y);
            float cn0 = fmaf(f0, c1[2*p],     i0 * g0);
            float cn1 = fmaf(f1, c1[2*p + 1], i1 * g1);
            c1[2*p] = cn0; c1[2*p + 1] = cn1;
            float h0 = o0 * tanh_fast(cn0);
            float h1 = o1 * tanh_fast(cn1);
            ull hp = pack2(h0, h1);
            *(ull*)(h1b + j * HS + q8 + 2 * p) = hp;   // next-step layer1 input
            *(ull*)(h2b + j * HS + q8 + 2 * p) = hp;   // this-step layer2 input
        }
        if (ldx) {
            xb[0 * HS + tid] = xnext.x; xb[1 * HS + tid] = xnext.y;
            xb[2 * HS + tid] = xnext.z; xb[3 * HS + tid] = xnext.w;
        }
        __syncthreads();   // sync2: h2b rows 0..63 ready

        // ================= Phase C: layer-2 gates (K=128: [h1_t ; h2_{t-1}]) =====
        #pragma unroll
        for (int gg = 0; gg < 4; gg++)
            #pragma unroll
            for (int p = 0; p < 4; p++)
                acc[gg][p] = bs2[gg];

        #pragma unroll 4
        for (int k = 0; k < 128; k++) {
            float4 w4 = W2v[(k << 6) | j];
            ull w0 = splat2(w4.x), w1 = splat2(w4.y);
            ull w2 = splat2(w4.z), w3 = splat2(w4.w);
            const ull* hp = (const ull*)(h2b + k * HS + q8);
            #pragma unroll
            for (int p = 0; p < 4; p++) {
                ull hv = hp[p];
                acc[0][p] = fma2(hv, w0, acc[0][p]);
                acc[1][p] = fma2(hv, w1, acc[1][p]);
                acc[2][p] = fma2(hv, w2, acc[2][p]);
                acc[3][p] = fma2(hv, w3, acc[3][p]);
            }
        }
        __syncthreads();   // sync3: all threads read h2b before rows 64..127 overwrite

        // ================= Phase D: layer-2 elementwise =================
        #pragma unroll
        for (int p = 0; p < 4; p++) {
            float2 gi = unpack2(acc[0][p]);
            float2 gf = unpack2(acc[1][p]);
            float2 gc = unpack2(acc[2][p]);
            float2 go = unpack2(acc[3][p]);
            float i0 = sigf(gi.x),      i1 = sigf(gi.y);
            float f0 = sigf(gf.x),      f1 = sigf(gf.y);
            float g0 = tanh_fast(gc.x), g1 = tanh_fast(gc.y);
            float o0 = sigf(go.x),      o1 = sigf(go.y);
            float cn0 = fmaf(f0, c2[2*p],     i0 * g0);
            float cn1 = fmaf(f1, c2[2*p + 1], i1 * g1);
            c2[2*p] = cn0; c2[2*p + 1] = cn1;
            float h0 = o0 * tanh_fast(cn0);
            float h1 = o1 * tanh_fast(cn1);
            *(ull*)(h2b + (64 + j) * HS + q8 + 2 * p) = pack2(h0, h1);
        }
        // no sync: next Phase A touches h1b/xb only; D->C' ordered via sync1'+sync2'
    }
    __syncthreads();

    // ================= FC head: out[b] = h2_final @ Wfc^T + bfc =================
    for (int tt = tid; tt < TB * 20; tt += NTH) {
        int bb = tt / 20, o = tt % 20;
        float s = bfc[o];
        #pragma unroll 8
        for (int jj = 0; jj < 64; jj++)
            s += h2b[(64 + jj) * HS + bb] * Wfc[o * 64 + jj];
        out[(size_t)(b0 + bb) * 20 + o] = s;
    }
}

extern "C" void kernel_launch(void* const* d_in, const int* in_sizes, int n_in,
                              void* d_out, int out_size) {
    const float* x    = (const float*)d_in[0];
    const float* Wih0 = (const float*)d_in[1];
    const float* Whh0 = (const float*)d_in[2];
    const float* bih0 = (const float*)d_in[3];
    const float* bhh0 = (const float*)d_in[4];
    const float* Wih1 = (const float*)d_in[5];
    const float* Whh1 = (const float*)d_in[6];
    const float* bih1 = (const float*)d_in[7];
    const float* bhh1 = (const float*)d_in[8];
    const float* Wfc  = (const float*)d_in[9];
    const float* bfc  = (const float*)d_in[10];
    float* out = (float*)d_out;

    const size_t smem = (size_t)SM_TOT * sizeof(float);
    cudaFuncSetAttribute(lstm2_fused_kernel,
                         cudaFuncAttributeMaxDynamicSharedMemorySize, (int)smem);
    lstm2_fused_kernel<<<B_TOT / TB, NTH, smem>>>(
        x, Wih0, Whh0, bih0, bhh0, Wih1, Whh1, bih1, bhh1, Wfc, bfc, out);
}

// round 11
// speedup vs baseline: 1.0636x; 1.0636x over previous
#include <cuda_runtime.h>

#define B_TOT   4096
#define T_STEPS 512
#define IN_W    4
#define H_DIM   64
#define TB      32
#define NTH     256
#define HS      36   // padded batch-row stride (floats), 16B-aligned rows for LDS.128

typedef unsigned long long ull;

// ---- sm_103a packed f32x2 helpers ----
__device__ __forceinline__ ull splat2(float x) {
    ull r; asm("mov.b64 %0, {%1, %1};" : "=l"(r) : "f"(x)); return r;
}
__device__ __forceinline__ ull pack2(float lo, float hi) {
    ull r; asm("mov.b64 %0, {%1, %2};" : "=l"(r) : "f"(lo), "f"(hi)); return r;
}
__device__ __forceinline__ ull fma2(ull a, ull b, ull c) {
    ull d; asm("fma.rn.f32x2 %0, %1, %2, %3;" : "=l"(d) : "l"(a), "l"(b), "l"(c)); return d;
}
__device__ __forceinline__ float2 unpack2(ull v) {
    float2 f; asm("mov.b64 {%0, %1}, %2;" : "=f"(f.x), "=f"(f.y) : "l"(v)); return f;
}

// ---- HW activations (MUFU.TANH) ----
__device__ __forceinline__ float tanhx(float x) {
    float y; asm("tanh.approx.f32 %0, %1;" : "=f"(y) : "f"(x)); return y;
}
__device__ __forceinline__ float sigx(float x) {
    return fmaf(tanhx(0.5f * x), 0.5f, 0.5f);
}

// SMEM layout (floats):
//  W1   [64][256]  @ 0       (Whh0, transposed, gate-interleaved [k][j][g])
//  W2   [128][256] @ 16384   (rows 0..63: Wih1, rows 64..127: Whh1)
//  h1b  [64][HS]   @ 49152   (h1 state, [unit][batch]; also layer-2 input rows 0..63)
//  h2b  [64][HS]   @ 51456   (h2 state)
//  xb   [4][HS]    @ 53760   (x_t, [in_feature][batch])
#define SM_W2   16384
#define SM_H1B  49152
#define SM_H2B  51456
#define SM_XB   53760
#define SM_TOT  53904   // floats = 215616 bytes

__global__ void __launch_bounds__(NTH, 1) lstm2_fused_kernel(
    const float* __restrict__ x,
    const float* __restrict__ Wih0, const float* __restrict__ Whh0,
    const float* __restrict__ bih0, const float* __restrict__ bhh0,
    const float* __restrict__ Wih1, const float* __restrict__ Whh1,
    const float* __restrict__ bih1, const float* __restrict__ bhh1,
    const float* __restrict__ Wfc,  const float* __restrict__ bfc,
    float* __restrict__ out)
{
    extern __shared__ float sm[];
    float* W1  = sm;
    float* W2  = sm + SM_W2;
    float* h1b = sm + SM_H1B;
    float* h2b = sm + SM_H2B;
    float* xb  = sm + SM_XB;

    const int tid = threadIdx.x;
    const int j   = tid & 63;   // gate unit
    const int q   = tid >> 6;   // batch quarter (8 batches each)
    const int b0  = blockIdx.x * TB;

    // ---- prologue: stage weights into SMEM, transposed + gate-interleaved ----
    for (int idx = tid; idx < 64 * 256; idx += NTH) {
        int k = idx >> 8, col = idx & 255;
        int r = ((col & 3) << 6) | (col >> 2);   // original gate row
        W1[idx] = Whh0[r * 64 + k];
    }
    for (int idx = tid; idx < 128 * 256; idx += NTH) {
        int k = idx >> 8, col = idx & 255;
        int r = ((col & 3) << 6) | (col >> 2);
        W2[idx] = (k < 64) ? Wih1[r * 64 + k] : Whh1[r * 64 + (k - 64)];
    }
    for (int idx = tid; idx < 64 * HS; idx += NTH) { h1b[idx] = 0.f; h2b[idx] = 0.f; }
    if (tid < TB) {
        const float4 x4 = *(const float4*)(x + ((size_t)(b0 + tid) * T_STEPS) * IN_W);
        xb[0 * HS + tid] = x4.x; xb[1 * HS + tid] = x4.y;
        xb[2 * HS + tid] = x4.z; xb[3 * HS + tid] = x4.w;
    }

    // per-thread constants: input weights (layer1) + fused biases (pre-splatted)
    float wx[4][4];
    ull bs1[4], bs2[4];
    #pragma unroll
    for (int gg = 0; gg < 4; gg++) {
        int r = gg * 64 + j;
        #pragma unroll
        for (int ii = 0; ii < IN_W; ii++) wx[gg][ii] = Wih0[r * IN_W + ii];
        bs1[gg] = splat2(bih0[r] + bhh0[r]);
        bs2[gg] = splat2(bih1[r] + bhh1[r]);
    }

    float c1[8], c2[8];
    #pragma unroll
    for (int i = 0; i < 8; i++) { c1[i] = 0.f; c2[i] = 0.f; }

    __syncthreads();

    const float4* W1v = (const float4*)W1;
    const float4* W2v = (const float4*)W2;
    const int q8 = q * 8;

    for (int t = 0; t < T_STEPS; t++) {
        // ================= Phase A: layer-1 gates =================
        ull acc[4][4];
        #pragma unroll
        for (int gg = 0; gg < 4; gg++)
            #pragma unroll
            for (int p = 0; p < 4; p++)
                acc[gg][p] = bs1[gg];

        // x_t contribution (K=4, weights in registers)
        #pragma unroll
        for (int ii = 0; ii < IN_W; ii++) {
            ull xw0 = splat2(wx[0][ii]), xw1 = splat2(wx[1][ii]);
            ull xw2 = splat2(wx[2][ii]), xw3 = splat2(wx[3][ii]);
            const ulonglong2 xv01 = *(const ulonglong2*)(xb + ii * HS + q8);
            const ulonglong2 xv23 = *(const ulonglong2*)(xb + ii * HS + q8 + 4);
            ull xv[4] = { xv01.x, xv01.y, xv23.x, xv23.y };
            #pragma unroll
            for (int p = 0; p < 4; p++) {
                acc[0][p] = fma2(xv[p], xw0, acc[0][p]);
                acc[1][p] = fma2(xv[p], xw1, acc[1][p]);
                acc[2][p] = fma2(xv[p], xw2, acc[2][p]);
                acc[3][p] = fma2(xv[p], xw3, acc[3][p]);
            }
        }
        // h1_{t-1} @ Whh0^T  (K=64)
        #pragma unroll 8
        for (int k = 0; k < 64; k++) {
            float4 w4 = W1v[(k << 6) | j];
            const ulonglong2 h01 = *(const ulonglong2*)(h1b + k * HS + q8);
            const ulonglong2 h23 = *(const ulonglong2*)(h1b + k * HS + q8 + 4);
            ull w0 = splat2(w4.x), w1 = splat2(w4.y);
            ull w2 = splat2(w4.z), w3 = splat2(w4.w);
            ull hv[4] = { h01.x, h01.y, h23.x, h23.y };
            #pragma unroll
            for (int p = 0; p < 4; p++) {
                acc[0][p] = fma2(hv[p], w0, acc[0][p]);
                acc[1][p] = fma2(hv[p], w1, acc[1][p]);
                acc[2][p] = fma2(hv[p], w2, acc[2][p]);
                acc[3][p] = fma2(hv[p], w3, acc[3][p]);
            }
        }
        __syncthreads();   // sync1: all gates read h1b/xb before overwrite

        // ================= Phase B: layer-1 elementwise =================
        float4 xnext;
        const bool ldx = (tid < TB) && (t + 1 < T_STEPS);
        if (ldx)
            xnext = *(const float4*)(x + ((size_t)(b0 + tid) * T_STEPS + (t + 1)) * IN_W);

        #pragma unroll
        for (int p = 0; p < 4; p++) {
            float2 gi = unpack2(acc[0][p]);
            float2 gf = unpack2(acc[1][p]);
            float2 gc = unpack2(acc[2][p]);
            float2 go = unpack2(acc[3][p]);
            float i0 = sigx(gi.x),  i1 = sigx(gi.y);
            float f0 = sigx(gf.x),  f1 = sigx(gf.y);
            float g0 = tanhx(gc.x), g1 = tanhx(gc.y);
            float o0 = sigx(go.x),  o1 = sigx(go.y);
            float cn0 = fmaf(f0, c1[2*p],     i0 * g0);
            float cn1 = fmaf(f1, c1[2*p + 1], i1 * g1);
            c1[2*p] = cn0; c1[2*p + 1] = cn1;
            float h0 = o0 * tanhx(cn0);
            float h1 = o1 * tanhx(cn1);
            *(ull*)(h1b + j * HS + q8 + 2 * p) = pack2(h0, h1);
        }
        if (ldx) {
            xb[0 * HS + tid] = xnext.x; xb[1 * HS + tid] = xnext.y;
            xb[2 * HS + tid] = xnext.z; xb[3 * HS + tid] = xnext.w;
        }
        __syncthreads();   // sync2: h1b (layer-2 input rows) ready

        // ============ Phase C: layer-2 gates (K=128: [h1_t ; h2_{t-1}]) ============
        #pragma unroll
        for (int gg = 0; gg < 4; gg++)
            #pragma unroll
            for (int p = 0; p < 4; p++)
                acc[gg][p] = bs2[gg];

        #pragma unroll 4
        for (int k = 0; k < 64; k++) {
            float4 w4 = W2v[(k << 6) | j];
            const ulonglong2 h01 = *(const ulonglong2*)(h1b + k * HS + q8);
            const ulonglong2 h23 = *(const ulonglong2*)(h1b + k * HS + q8 + 4);
            ull w0 = splat2(w4.x), w1 = splat2(w4.y);
            ull w2 = splat2(w4.z), w3 = splat2(w4.w);
            ull hv[4] = { h01.x, h01.y, h23.x, h23.y };
            #pragma unroll
            for (int p = 0; p < 4; p++) {
                acc[0][p] = fma2(hv[p], w0, acc[0][p]);
                acc[1][p] = fma2(hv[p], w1, acc[1][p]);
                acc[2][p] = fma2(hv[p], w2, acc[2][p]);
                acc[3][p] = fma2(hv[p], w3, acc[3][p]);
            }
        }
        #pragma unroll 4
        for (int k = 0; k < 64; k++) {
            float4 w4 = W2v[((64 + k) << 6) | j];
            const ulonglong2 h01 = *(const ulonglong2*)(h2b + k * HS + q8);
            const ulonglong2 h23 = *(const ulonglong2*)(h2b + k * HS + q8 + 4);
            ull w0 = splat2(w4.x), w1 = splat2(w4.y);
            ull w2 = splat2(w4.z), w3 = splat2(w4.w);
            ull hv[4] = { h01.x, h01.y, h23.x, h23.y };
            #pragma unroll
            for (int p = 0; p < 4; p++) {
                acc[0][p] = fma2(hv[p], w0, acc[0][p]);
                acc[1][p] = fma2(hv[p], w1, acc[1][p]);
                acc[2][p] = fma2(hv[p], w2, acc[2][p]);
                acc[3][p] = fma2(hv[p], w3, acc[3][p]);
            }
        }
        __syncthreads();   // sync3: all threads done reading h2b before D overwrites

        // ================= Phase D: layer-2 elementwise =================
        #pragma unroll
        for (int p = 0; p < 4; p++) {
            float2 gi = unpack2(acc[0][p]);
            float2 gf = unpack2(acc[1][p]);
            float2 gc = unpack2(acc[2][p]);
            float2 go = unpack2(acc[3][p]);
            float i0 = sigx(gi.x),  i1 = sigx(gi.y);
            float f0 = sigx(gf.x),  f1 = sigx(gf.y);
            float g0 = tanhx(gc.x), g1 = tanhx(gc.y);
            float o0 = sigx(go.x),  o1 = sigx(go.y);
            float cn0 = fmaf(f0, c2[2*p],     i0 * g0);
            float cn1 = fmaf(f1, c2[2*p + 1], i1 * g1);
            c2[2*p] = cn0; c2[2*p + 1] = cn1;
            float h0 = o0 * tanhx(cn0);
            float h1 = o1 * tanhx(cn1);
            *(ull*)(h2b + j * HS + q8 + 2 * p) = pack2(h0, h1);
        }
        // no sync needed: next Phase A touches h1b/xb only; D->C' ordered by sync1'+sync2'
    }
    __syncthreads();

    // ================= FC head: out[b] = h2_final @ Wfc^T + bfc =================
    for (int tt = tid; tt < TB * 20; tt += NTH) {
        int bb = tt / 20, o = tt % 20;
        float s = bfc[o];
        #pragma unroll 8
        for (int jj = 0; jj < 64; jj++)
            s += h2b[jj * HS + bb] * Wfc[o * 64 + jj];
        out[(size_t)(b0 + bb) * 20 + o] = s;
    }
}

extern "C" void kernel_launch(void* const* d_in, const int* in_sizes, int n_in,
                              void* d_out, int out_size) {
    const float* x    = (const float*)d_in[0];
    const float* Wih0 = (const float*)d_in[1];
    const float* Whh0 = (const float*)d_in[2];
    const float* bih0 = (const float*)d_in[3];
    const float* bhh0 = (const float*)d_in[4];
    const float* Wih1 = (const float*)d_in[5];
    const float* Whh1 = (const float*)d_in[6];
    const float* bih1 = (const float*)d_in[7];
    const float* bhh1 = (const float*)d_in[8];
    const float* Wfc  = (const float*)d_in[9];
    const float* bfc  = (const float*)d_in[10];
    float* out = (float*)d_out;

    const size_t smem = (size_t)SM_TOT * sizeof(float);
    cudaFuncSetAttribute(lstm2_fused_kernel,
                         cudaFuncAttributeMaxDynamicSharedMemorySize, (int)smem);
    lstm2_fused_kernel<<<B_TOT / TB, NTH, smem>>>(
        x, Wih0, Whh0, bih0, bhh0, Wih1, Whh1, bih1, bhh1, Wfc, bfc, out);
}